// round 1
// baseline (speedup 1.0000x reference)
#include <cuda_runtime.h>
#include <cstdint>

// out = clip(low_img * c[b,c], 1e-8, 1) ** (mask==0 ? g1[b,c] : g2[b,c])
// B=16, C=3, H=512, W=512  -> 12,582,912 elements, HW = 262144 = 2^18.
// Pure elementwise, HBM-bound: ~151 MB total traffic.

#define HW_LOG2_VEC4 16   // (H*W)/4 = 65536 vec4 per (b,c) plane

__device__ __forceinline__ float fast_lg2(float x) {
    float y;
    asm("lg2.approx.f32 %0, %1;" : "=f"(y) : "f"(x));
    return y;
}
__device__ __forceinline__ float fast_ex2(float x) {
    float y;
    asm("ex2.approx.f32 %0, %1;" : "=f"(y) : "f"(x));
    return y;
}

__device__ __forceinline__ float apply_one(float x, int m, float cc, float G1, float G2) {
    float t = fminf(fmaxf(x * cc, 1e-8f), 1.0f);
    float g = (m == 0) ? G1 : G2;
    return fast_ex2(g * fast_lg2(t));
}

__global__ void __launch_bounds__(256)
net_gamma_kernel(const float4* __restrict__ low,
                 const int4*   __restrict__ mask,
                 const float*  __restrict__ g1,
                 const float*  __restrict__ g2,
                 const float*  __restrict__ c,
                 float4*       __restrict__ out,
                 int n4)
{
    int i = blockIdx.x * blockDim.x + threadIdx.x;
    if (i >= n4) return;

    int bc = i >> HW_LOG2_VEC4;          // uniform across each warp
    float cc = __ldg(c  + bc);
    float G1 = __ldg(g1 + bc);
    float G2 = __ldg(g2 + bc);

    float4 v = low[i];
    int4   m = mask[i];

    float4 o;
    o.x = apply_one(v.x, m.x, cc, G1, G2);
    o.y = apply_one(v.y, m.y, cc, G1, G2);
    o.z = apply_one(v.z, m.z, cc, G1, G2);
    o.w = apply_one(v.w, m.w, cc, G1, G2);

    out[i] = o;
}

extern "C" void kernel_launch(void* const* d_in, const int* in_sizes, int n_in,
                              void* d_out, int out_size)
{
    // metadata order: low_img [B,C,H,W] f32, g1 [B,C] f32, g2 [B,C] f32,
    //                 c [B,C] f32, I_Mask [B,C,H,W] i32
    const float4* low  = (const float4*)d_in[0];
    const float*  g1   = (const float*)d_in[1];
    const float*  g2   = (const float*)d_in[2];
    const float*  c    = (const float*)d_in[3];
    const int4*   mask = (const int4*)d_in[4];
    float4* out = (float4*)d_out;

    int n4 = out_size / 4;               // 3,145,728
    int threads = 256;
    int blocks = (n4 + threads - 1) / threads;   // 12288
    net_gamma_kernel<<<blocks, threads>>>(low, mask, g1, g2, c, out, n4);
}

// round 2
// speedup vs baseline: 1.0354x; 1.0354x over previous
#include <cuda_runtime.h>
#include <cstdint>

// out = clip(low_img * c[b,c], 1e-8, 1) ** (mask==0 ? g1[b,c] : g2[b,c])
// B=16, C=3, H=512, W=512 -> 12,582,912 elems; HW/4 = 65536 vec4 per plane.
// HBM-bound (~151 MB traffic). This round: 2x vec4 per thread, all 4 loads
// front-batched for MLP, streaming cache hints.

#define HW_LOG2_VEC4 16

__device__ __forceinline__ float fast_lg2(float x) {
    float y; asm("lg2.approx.f32 %0, %1;" : "=f"(y) : "f"(x)); return y;
}
__device__ __forceinline__ float fast_ex2(float x) {
    float y; asm("ex2.approx.f32 %0, %1;" : "=f"(y) : "f"(x)); return y;
}

__device__ __forceinline__ float apply_one(float x, int m, float cc, float G1, float G2) {
    float t = fminf(fmaxf(x * cc, 1e-8f), 1.0f);
    float g = (m == 0) ? G1 : G2;
    return fast_ex2(g * fast_lg2(t));
}

__device__ __forceinline__ float4 apply_vec(float4 v, int4 m, int bc,
                                            const float* __restrict__ g1,
                                            const float* __restrict__ g2,
                                            const float* __restrict__ c) {
    float cc = __ldg(c  + bc);
    float G1 = __ldg(g1 + bc);
    float G2 = __ldg(g2 + bc);
    float4 o;
    o.x = apply_one(v.x, m.x, cc, G1, G2);
    o.y = apply_one(v.y, m.y, cc, G1, G2);
    o.z = apply_one(v.z, m.z, cc, G1, G2);
    o.w = apply_one(v.w, m.w, cc, G1, G2);
    return o;
}

__global__ void __launch_bounds__(256)
net_gamma_kernel(const float4* __restrict__ low,
                 const int4*   __restrict__ mask,
                 const float*  __restrict__ g1,
                 const float*  __restrict__ g2,
                 const float*  __restrict__ c,
                 float4*       __restrict__ out,
                 int n4)
{
    // Each block covers 2*256 consecutive vec4s; each thread does 2,
    // stride blockDim apart (both segments fully coalesced).
    int i0 = blockIdx.x * (blockDim.x * 2) + threadIdx.x;
    int i1 = i0 + blockDim.x;

    if (i1 < n4) {
        // Front-batch all 4 global loads (64 B in flight per thread).
        float4 v0 = __ldcs(low  + i0);
        float4 v1 = __ldcs(low  + i1);
        int4   m0 = __ldcs(mask + i0);
        int4   m1 = __ldcs(mask + i1);

        float4 o0 = apply_vec(v0, m0, i0 >> HW_LOG2_VEC4, g1, g2, c);
        float4 o1 = apply_vec(v1, m1, i1 >> HW_LOG2_VEC4, g1, g2, c);

        __stcs(out + i0, o0);
        __stcs(out + i1, o1);
    } else if (i0 < n4) {
        float4 v0 = __ldcs(low  + i0);
        int4   m0 = __ldcs(mask + i0);
        __stcs(out + i0, apply_vec(v0, m0, i0 >> HW_LOG2_VEC4, g1, g2, c));
    }
}

extern "C" void kernel_launch(void* const* d_in, const int* in_sizes, int n_in,
                              void* d_out, int out_size)
{
    const float4* low  = (const float4*)d_in[0];
    const float*  g1   = (const float*)d_in[1];
    const float*  g2   = (const float*)d_in[2];
    const float*  c    = (const float*)d_in[3];
    const int4*   mask = (const int4*)d_in[4];
    float4* out = (float4*)d_out;

    int n4 = out_size / 4;                       // 3,145,728
    int threads = 256;
    int per_block = threads * 2;
    int blocks = (n4 + per_block - 1) / per_block;   // 6144
    net_gamma_kernel<<<blocks, threads>>>(low, mask, g1, g2, c, out, n4);
}